// round 5
// baseline (speedup 1.0000x reference)
#include <cuda_runtime.h>
#include <cstddef>

// Problem constants
#define NB   1024
#define NT   1024
#define KQ   15
#define KT   20
#define NDOF 7

// Output layout offsets (fp32 elements), total = 38,827,009
static constexpr size_t OFF_MODEL       = 0;
static constexpr size_t OFF_QDOT_LOSS   = 1;
static constexpr size_t OFF_QDDOT_LOSS  = 1 + 7168;
static constexpr size_t OFF_QDDDOT_LOSS = 1 + 2 * 7168;
static constexpr size_t OFF_TORQUE_LOSS = 1 + 3 * 7168;
static constexpr size_t OFF_Q           = 1 + 4 * 7168;           // 28673 (== 1 mod 4)
static constexpr size_t QTD             = (size_t)NB * NT * NDOF; // 7,340,032
static constexpr size_t OFF_QDOT        = OFF_Q + QTD;
static constexpr size_t OFF_QDDOT       = OFF_Q + 2 * QTD;
static constexpr size_t OFF_QDDDOT      = OFF_Q + 3 * QTD;
static constexpr size_t OFF_TORQUE      = OFF_Q + 4 * QTD;
static constexpr size_t OFF_T           = OFF_Q + 5 * QTD;
static constexpr size_t OFF_TCUM        = OFF_T + NB;
static constexpr size_t OFF_DT          = OFF_TCUM + (size_t)NB * NT;

__device__ __forceinline__ float huber_pos(float x) {
    // x >= 0 guaranteed (relu output), delta = 1
    return x < 1.0f ? 0.5f * x * x : x - 0.5f;
}

// ---------------------------------------------------------------------------
// Kernel 1: per-batch dt, inclusive cumsum, total time t.
// 512 blocks x 1024 threads; each block handles 2 batches; Nt row in regs.
// ---------------------------------------------------------------------------
__global__ __launch_bounds__(1024)
void scan_kernel(const float* __restrict__ t_cps,
                 const float* __restrict__ Nt,
                 float* __restrict__ out)
{
    __shared__ float s_w[32];
    const int t    = threadIdx.x;
    const int lane = t & 31;
    const int wid  = t >> 5;

    float nt[KT];
#pragma unroll
    for (int k = 0; k < KT; k++) nt[k] = Nt[t * KT + k];

    const int b0 = blockIdx.x * 2;
#pragma unroll
    for (int bi = 0; bi < 2; bi++) {
        const int b = b0 + bi;
        float dtau = 0.0f;
#pragma unroll
        for (int k = 0; k < KT; k++) dtau = fmaf(nt[k], __ldg(&t_cps[b * KT + k]), dtau);
        const float dt = 1.0f / (dtau * (float)NT);

        // block-wide inclusive scan of dt
        float v = dt;
#pragma unroll
        for (int off = 1; off < 32; off <<= 1) {
            float u = __shfl_up_sync(0xffffffffu, v, off);
            if (lane >= off) v += u;
        }
        if (lane == 31) s_w[wid] = v;
        __syncthreads();
        if (wid == 0) {
            float wv = s_w[lane];
#pragma unroll
            for (int off = 1; off < 32; off <<= 1) {
                float u = __shfl_up_sync(0xffffffffu, wv, off);
                if (lane >= off) wv += u;
            }
            s_w[lane] = wv;
        }
        __syncthreads();
        float c = v + (wid > 0 ? s_w[wid - 1] : 0.0f);

        out[OFF_DT   + (size_t)b * NT + t] = dt;
        out[OFF_TCUM + (size_t)b * NT + t] = c;
        if (t == NT - 1) out[OFF_T + b] = c;
        if (bi == 0) __syncthreads(); // protect s_w before next iteration
    }
}

// ---------------------------------------------------------------------------
// Warp-cooperative vectorized store of a 224-float contiguous chunk whose
// global float offset is ==1 (mod 4). Lane l owns values j = 7l..7l+6.
// Stage into buf at [j+1], then: edges j=0,1,2,223 scalar; body 55x STG.128.
// ---------------------------------------------------------------------------
__device__ __forceinline__ void store_chunk(float* __restrict__ g,
                                            float* __restrict__ buf,
                                            const float v[7], int lane)
{
#pragma unroll
    for (int d = 0; d < 7; d++) buf[1 + 7 * lane + d] = v[d];  // conflict-free (gcd(7,32)=1)
    __syncwarp();
    // body: float4 slots s=1..55 cover j = 4s-1 .. 4s+2 ; g + (4s-1) is 16B-aligned
    float4 x0 = *(const float4*)(buf + 4 * (lane + 1));
    *(float4*)(g + 4 * (lane + 1) - 1) = x0;
    if (lane < 23) {
        float4 x1 = *(const float4*)(buf + 4 * (lane + 33));
        *(float4*)(g + 4 * (lane + 33) - 1) = x1;
    }
    if (lane < 3)       g[lane] = buf[lane + 1];
    else if (lane == 3) g[223]  = buf[224];
    __syncwarp();
}

// ---------------------------------------------------------------------------
// Kernel 2: main streaming kernel.
// Tile: T_TILE=64 timesteps x B_TILE=8 batches, 256 threads (warp = batch).
// q-basis packed float4 {N,dN,ddN,dddN} in SMEM (pad-17 rows, conflict-free
// LDS.128); t-basis scalar planes; outputs staged per-warp then STG.128.
// ---------------------------------------------------------------------------
#define T_TILE 64
#define B_TILE 8
#define THR    256

__global__ __launch_bounds__(THR)
void main_kernel(const float* __restrict__ q_cps, const float* __restrict__ t_cps,
                 const float* __restrict__ N,   const float* __restrict__ dN,
                 const float* __restrict__ ddN, const float* __restrict__ dddN,
                 const float* __restrict__ Nt,  const float* __restrict__ dNt,
                 const float* __restrict__ ddNt,
                 const float* __restrict__ Ldot, const float* __restrict__ Lddot,
                 const float* __restrict__ Ldddot,
                 float* __restrict__ out)
{
    __shared__ float4 s_qb[T_TILE][17];          // [lt][k] = {N,dN,ddN,dddN}, pad 17
    __shared__ float  s_tbs[3 * KT][T_TILE];     // rows: Nt(0-19) dNt(20-39) ddNt(40-59)
    __shared__ float  s_qc[B_TILE][KQ][8];       // padded to 8 for float4 broadcast
    __shared__ float  s_tc[B_TILE][KT];
    __shared__ float  s_lims[24];
    __shared__ float  s_stage[B_TILE][240];      // per-warp staging (16B-aligned rows)

    const int tid = threadIdx.x;
    const int t0  = blockIdx.x * T_TILE;
    const int b0  = blockIdx.y * B_TILE;

    {
        const float* qa[4] = {N, dN, ddN, dddN};
#pragma unroll
        for (int a = 0; a < 4; a++) {
            const float* src = qa[a];
            for (int idx = tid; idx < T_TILE * KQ; idx += THR) {
                int lt = idx / KQ, k = idx % KQ;
                ((float*)&s_qb[lt][k])[a] = src[(t0 + lt) * KQ + k];
            }
        }
        const float* ta[3] = {Nt, dNt, ddNt};
#pragma unroll
        for (int a = 0; a < 3; a++) {
            const float* src = ta[a];
            for (int idx = tid; idx < T_TILE * KT; idx += THR) {
                int lt = idx / KT, k = idx % KT;
                s_tbs[a * KT + k][lt] = src[(t0 + lt) * KT + k];
            }
        }
    }
    for (int idx = tid; idx < B_TILE * KQ * NDOF; idx += THR) {
        int w = idx / (KQ * NDOF), r = idx % (KQ * NDOF);
        s_qc[w][r / NDOF][r % NDOF] = q_cps[(size_t)(b0) * KQ * NDOF + idx];
    }
    for (int idx = tid; idx < B_TILE * KT; idx += THR)
        s_tc[idx / KT][idx % KT] = t_cps[b0 * KT + idx];
    if (tid < 7) {
        s_lims[tid]      = Ldot[tid];
        s_lims[7 + tid]  = Lddot[tid];
        s_lims[14 + tid] = Ldddot[tid];
    }
    __syncthreads();

    const int lane = tid & 31;
    const int w    = tid >> 5;   // local batch 0..7
    const int b    = b0 + w;
    float* buf = s_stage[w];

    float accd[7]   = {0,0,0,0,0,0,0};
    float accdd[7]  = {0,0,0,0,0,0,0};
    float accddd[7] = {0,0,0,0,0,0,0};

#pragma unroll
    for (int i = 0; i < 2; i++) {
        const int lt = lane + 32 * i;

        float dtau = 0.0f, ddtau = 0.0f, dddtau = 0.0f;
#pragma unroll
        for (int k = 0; k < KT; k++) {
            float tc = s_tc[w][k];
            dtau   = fmaf(s_tbs[k][lt],          tc, dtau);
            ddtau  = fmaf(s_tbs[KT + k][lt],     tc, ddtau);
            dddtau = fmaf(s_tbs[2 * KT + k][lt], tc, dddtau);
        }

        float q[7]    = {0,0,0,0,0,0,0};
        float qd[7]   = {0,0,0,0,0,0,0};
        float qdd[7]  = {0,0,0,0,0,0,0};
        float qddd[7] = {0,0,0,0,0,0,0};
#pragma unroll
        for (int k = 0; k < KQ; k++) {
            float4 nb = s_qb[lt][k];
            float4 c0 = *(const float4*)&s_qc[w][k][0];   // broadcast
            float4 c1 = *(const float4*)&s_qc[w][k][4];   // broadcast
            float cs[7] = {c0.x, c0.y, c0.z, c0.w, c1.x, c1.y, c1.z};
#pragma unroll
            for (int d = 0; d < 7; d++) {
                q[d]    = fmaf(nb.x, cs[d], q[d]);
                qd[d]   = fmaf(nb.y, cs[d], qd[d]);
                qdd[d]  = fmaf(nb.z, cs[d], qdd[d]);
                qddd[d] = fmaf(nb.w, cs[d], qddd[d]);
            }
        }

        const float a  = dtau;
        const float a2 = a * a;
        const float a3 = a2 * a;
        const float dt = 1.0f / (a * (float)NT);
        const float c1v = ddtau * a;
        const float c2v = 3.0f * ddtau * a2;
        const float c3v = a2 * dddtau + ddtau * ddtau * a;

        float v1[7], v2[7], v3[7];
#pragma unroll
        for (int d = 0; d < 7; d++) {
            v1[d] = qd[d] * a;
            v2[d] = fmaf(qdd[d], a2, qd[d] * c1v);
            v3[d] = fmaf(qddd[d], a3, fmaf(qdd[d], c2v, qd[d] * c3v));
            accd[d]   += huber_pos(fmaxf(fabsf(v1[d]) - s_lims[d],      0.0f)) * dt;
            accdd[d]  += huber_pos(fmaxf(fabsf(v2[d]) - s_lims[7 + d],  0.0f)) * dt;
            accddd[d] += huber_pos(fmaxf(fabsf(v3[d]) - s_lims[14 + d], 0.0f)) * dt;
        }

        const size_t chunk = ((size_t)b * NT + t0 + 32 * i) * NDOF; // multiple of 224
        store_chunk(out + OFF_Q      + chunk, buf, q,  lane);
        store_chunk(out + OFF_QDOT   + chunk, buf, v1, lane);
        store_chunk(out + OFF_QDDOT  + chunk, buf, v2, lane);
        store_chunk(out + OFF_QDDDOT + chunk, buf, v3, lane);
    }

    // warp-reduce the 21 loss accumulators (all lanes same b)
#pragma unroll
    for (int d = 0; d < 7; d++) {
#pragma unroll
        for (int off = 16; off; off >>= 1) {
            accd[d]   += __shfl_xor_sync(0xffffffffu, accd[d],   off);
            accdd[d]  += __shfl_xor_sync(0xffffffffu, accdd[d],  off);
            accddd[d] += __shfl_xor_sync(0xffffffffu, accddd[d], off);
        }
    }
    if (lane == 0) {
#pragma unroll
        for (int d = 0; d < 7; d++) {
            atomicAdd(&out[OFF_QDOT_LOSS   + (size_t)b * NDOF + d], accd[d]);
            atomicAdd(&out[OFF_QDDOT_LOSS  + (size_t)b * NDOF + d], accdd[d]);
            atomicAdd(&out[OFF_QDDDOT_LOSS + (size_t)b * NDOF + d], accddd[d]);
        }
    }
}

// ---------------------------------------------------------------------------
// Kernel 3: model_loss = sum of q_dot/q_ddot/q_dddot losses (21504 floats)
// ---------------------------------------------------------------------------
__global__ __launch_bounds__(1024)
void finalize_kernel(float* __restrict__ out)
{
    __shared__ float s[32];
    float v = 0.0f;
    for (int i = threadIdx.x; i < 3 * NB * NDOF; i += 1024)
        v += out[1 + i];
#pragma unroll
    for (int off = 16; off; off >>= 1) v += __shfl_xor_sync(0xffffffffu, v, off);
    if ((threadIdx.x & 31) == 0) s[threadIdx.x >> 5] = v;
    __syncthreads();
    if (threadIdx.x < 32) {
        v = s[threadIdx.x];
#pragma unroll
        for (int off = 16; off; off >>= 1) v += __shfl_xor_sync(0xffffffffu, v, off);
        if (threadIdx.x == 0) out[OFF_MODEL] = v;
    }
}

// ---------------------------------------------------------------------------
extern "C" void kernel_launch(void* const* d_in, const int* in_sizes, int n_in,
                              void* d_out, int out_size)
{
    const float* q_cps  = (const float*)d_in[0];
    const float* t_cps  = (const float*)d_in[1];
    const float* N      = (const float*)d_in[2];
    const float* dN     = (const float*)d_in[3];
    const float* ddN    = (const float*)d_in[4];
    const float* dddN   = (const float*)d_in[5];
    const float* Nt     = (const float*)d_in[6];
    const float* dNt    = (const float*)d_in[7];
    const float* ddNt   = (const float*)d_in[8];
    const float* Ldot   = (const float*)d_in[9];
    const float* Lddot  = (const float*)d_in[10];
    const float* Ldddot = (const float*)d_in[11];
    // d_in[12] = torque_limits (unused: torque == 0 -> torque_loss == 0)

    float* out = (float*)d_out;

    // zero model_loss + all four loss regions, and the torque output (all zeros)
    cudaMemsetAsync(out, 0, (size_t)OFF_Q * sizeof(float), 0);
    cudaMemsetAsync(out + OFF_TORQUE, 0, QTD * sizeof(float), 0);

    scan_kernel<<<512, 1024>>>(t_cps, Nt, out);

    dim3 grid(NT / T_TILE, NB / B_TILE); // (16, 128)
    main_kernel<<<grid, THR>>>(q_cps, t_cps, N, dN, ddN, dddN,
                               Nt, dNt, ddNt, Ldot, Lddot, Ldddot, out);

    finalize_kernel<<<1, 1024>>>(out);
}

// round 6
// speedup vs baseline: 1.1547x; 1.1547x over previous
#include <cuda_runtime.h>
#include <cstddef>

// Problem constants
#define NB   1024
#define NT   1024
#define KQ   15
#define KT   20
#define NDOF 7

// Output layout offsets (fp32 elements), total = 38,827,009
static constexpr size_t OFF_MODEL       = 0;
static constexpr size_t OFF_QDOT_LOSS   = 1;
static constexpr size_t OFF_QDDOT_LOSS  = 1 + 7168;
static constexpr size_t OFF_QDDDOT_LOSS = 1 + 2 * 7168;
static constexpr size_t OFF_TORQUE_LOSS = 1 + 3 * 7168;
static constexpr size_t OFF_Q           = 1 + 4 * 7168;           // 28673 (== 1 mod 4)
static constexpr size_t QTD             = (size_t)NB * NT * NDOF; // 7,340,032
static constexpr size_t OFF_QDOT        = OFF_Q + QTD;
static constexpr size_t OFF_QDDOT       = OFF_Q + 2 * QTD;
static constexpr size_t OFF_QDDDOT      = OFF_Q + 3 * QTD;
static constexpr size_t OFF_TORQUE      = OFF_Q + 4 * QTD;
static constexpr size_t OFF_T           = OFF_Q + 5 * QTD;
static constexpr size_t OFF_TCUM        = OFF_T + NB;
static constexpr size_t OFF_DT          = OFF_TCUM + (size_t)NB * NT;

// Scratch: per-(b,t) time-spline coefficients {a=dtau, ddtau, dddtau, dt}
__device__ float4 g_coeff[(size_t)NB * NT];   // 16 MB static device array

__device__ __forceinline__ float huber_pos(float x) {
    // x >= 0 guaranteed (relu output), delta = 1
    return x < 1.0f ? 0.5f * x * x : x - 0.5f;
}

// ---------------------------------------------------------------------------
// Kernel A: time-spline coefficients. Grid (32 t-tiles, 32 b-tiles), 1024 thr.
// Thread (tx = t-local 0..31, ty = b-local 0..31). Writes g_coeff + dt stream.
// ---------------------------------------------------------------------------
__global__ __launch_bounds__(1024)
void coeff_kernel(const float* __restrict__ t_cps,
                  const float* __restrict__ Nt,  const float* __restrict__ dNt,
                  const float* __restrict__ ddNt,
                  float* __restrict__ out)
{
    __shared__ float sB[3][KT][32];   // [plane][k][t-local]
    __shared__ float sT[32][KT];      // [b-local][k]

    const int tid = threadIdx.x;
    const int t0  = blockIdx.x * 32;
    const int b0  = blockIdx.y * 32;

    {
        const float* src[3] = {Nt, dNt, ddNt};
#pragma unroll
        for (int p = 0; p < 3; p++)
            for (int idx = tid; idx < 32 * KT; idx += 1024) {
                int lt = idx / KT, k = idx % KT;
                sB[p][k][lt] = src[p][(t0 + lt) * KT + k];
            }
    }
    for (int idx = tid; idx < 32 * KT; idx += 1024) {
        int bl = idx / KT, k = idx % KT;
        sT[bl][k] = t_cps[(b0 + bl) * KT + k];
    }
    __syncthreads();

    const int tx = tid & 31;
    const int ty = tid >> 5;
    const int b  = b0 + ty;
    const int t  = t0 + tx;

    float a = 0.0f, dd = 0.0f, ddd = 0.0f;
#pragma unroll
    for (int k = 0; k < KT; k++) {
        float c = sT[ty][k];          // broadcast within warp
        a   = fmaf(sB[0][k][tx], c, a);
        dd  = fmaf(sB[1][k][tx], c, dd);
        ddd = fmaf(sB[2][k][tx], c, ddd);
    }
    const float dt = 1.0f / (a * (float)NT);

    g_coeff[(size_t)b * NT + t] = make_float4(a, dd, ddd, dt);
    out[OFF_DT + (size_t)b * NT + t] = dt;
}

// ---------------------------------------------------------------------------
// Kernel B: per-batch inclusive cumsum of dt -> t_cumsum, t. Block = batch.
// ---------------------------------------------------------------------------
__global__ __launch_bounds__(1024)
void cumsum_kernel(float* __restrict__ out)
{
    __shared__ float s_w[32];
    const int t    = threadIdx.x;
    const int lane = t & 31;
    const int wid  = t >> 5;
    const int b    = blockIdx.x;

    float v = out[OFF_DT + (size_t)b * NT + t];
#pragma unroll
    for (int off = 1; off < 32; off <<= 1) {
        float u = __shfl_up_sync(0xffffffffu, v, off);
        if (lane >= off) v += u;
    }
    if (lane == 31) s_w[wid] = v;
    __syncthreads();
    if (wid == 0) {
        float wv = s_w[lane];
#pragma unroll
        for (int off = 1; off < 32; off <<= 1) {
            float u = __shfl_up_sync(0xffffffffu, wv, off);
            if (lane >= off) wv += u;
        }
        s_w[lane] = wv;
    }
    __syncthreads();
    float c = v + (wid > 0 ? s_w[wid - 1] : 0.0f);

    out[OFF_TCUM + (size_t)b * NT + t] = c;
    if (t == NT - 1) out[OFF_T + b] = c;
}

// ---------------------------------------------------------------------------
// Flush a staged 224-float chunk (data at buf[1..224]) to g (g%4 floats == 1):
// 55x STG.128 body + 4 scalar edges.
// ---------------------------------------------------------------------------
__device__ __forceinline__ void flush_chunk(float* __restrict__ g,
                                            const float* __restrict__ buf,
                                            int lane)
{
    float4 x0 = *(const float4*)(buf + 4 * (lane + 1));
    *(float4*)(g + 4 * (lane + 1) - 1) = x0;
    if (lane < 23) {
        float4 x1 = *(const float4*)(buf + 4 * (lane + 33));
        *(float4*)(g + 4 * (lane + 33) - 1) = x1;
    }
    if (lane < 3)       g[lane] = buf[lane + 1];
    else if (lane == 3) g[223]  = buf[224];
}

// ---------------------------------------------------------------------------
// Kernel C: main streaming kernel.
// Tile: T_TILE=64 x B_TILE=8 batches, 256 threads (warp = batch).
// Time-spline coeffs read from g_coeff. All four output streams staged in
// SMEM per i-iteration, then flushed with STG.128.
// ---------------------------------------------------------------------------
#define T_TILE 64
#define B_TILE 8
#define THR    256

__global__ __launch_bounds__(THR)
void main_kernel(const float* __restrict__ q_cps,
                 const float* __restrict__ N,   const float* __restrict__ dN,
                 const float* __restrict__ ddN, const float* __restrict__ dddN,
                 const float* __restrict__ Ldot, const float* __restrict__ Lddot,
                 const float* __restrict__ Ldddot,
                 float* __restrict__ out)
{
    __shared__ float4 s_qb[T_TILE][17];          // [lt][k] = {N,dN,ddN,dddN}, pad 17
    __shared__ float  s_qc[B_TILE][KQ][8];       // padded to 8 for float4 broadcast
    __shared__ float  s_lims[24];
    __shared__ float  s_stage[B_TILE][4][240];   // per-warp, 4 streams

    const int tid = threadIdx.x;
    const int t0  = blockIdx.x * T_TILE;
    const int b0  = blockIdx.y * B_TILE;

    {
        const float* qa[4] = {N, dN, ddN, dddN};
#pragma unroll
        for (int a = 0; a < 4; a++) {
            const float* src = qa[a];
            for (int idx = tid; idx < T_TILE * KQ; idx += THR) {
                int lt = idx / KQ, k = idx % KQ;
                ((float*)&s_qb[lt][k])[a] = src[(t0 + lt) * KQ + k];
            }
        }
    }
    for (int idx = tid; idx < B_TILE * KQ * NDOF; idx += THR) {
        int w = idx / (KQ * NDOF), r = idx % (KQ * NDOF);
        s_qc[w][r / NDOF][r % NDOF] = q_cps[(size_t)b0 * KQ * NDOF + idx];
    }
    if (tid < 7) {
        s_lims[tid]      = Ldot[tid];
        s_lims[7 + tid]  = Lddot[tid];
        s_lims[14 + tid] = Ldddot[tid];
    }
    __syncthreads();

    const int lane = tid & 31;
    const int w    = tid >> 5;   // local batch 0..7
    const int b    = b0 + w;

    float accd[7]   = {0,0,0,0,0,0,0};
    float accdd[7]  = {0,0,0,0,0,0,0};
    float accddd[7] = {0,0,0,0,0,0,0};

#pragma unroll
    for (int i = 0; i < 2; i++) {
        const int lt = lane + 32 * i;

        const float4 cf = g_coeff[(size_t)b * NT + t0 + lt];

        float q[7]    = {0,0,0,0,0,0,0};
        float qd[7]   = {0,0,0,0,0,0,0};
        float qdd[7]  = {0,0,0,0,0,0,0};
        float qddd[7] = {0,0,0,0,0,0,0};
#pragma unroll
        for (int k = 0; k < KQ; k++) {
            float4 nb = s_qb[lt][k];
            float4 c0 = *(const float4*)&s_qc[w][k][0];   // broadcast
            float4 c1 = *(const float4*)&s_qc[w][k][4];   // broadcast
            float cs[7] = {c0.x, c0.y, c0.z, c0.w, c1.x, c1.y, c1.z};
#pragma unroll
            for (int d = 0; d < 7; d++) {
                q[d]    = fmaf(nb.x, cs[d], q[d]);
                qd[d]   = fmaf(nb.y, cs[d], qd[d]);
                qdd[d]  = fmaf(nb.z, cs[d], qdd[d]);
                qddd[d] = fmaf(nb.w, cs[d], qddd[d]);
            }
        }

        const float a   = cf.x;
        const float a2  = a * a;
        const float a3  = a2 * a;
        const float dt  = cf.w;
        const float c1v = cf.y * a;
        const float c2v = 3.0f * cf.y * a2;
        const float c3v = fmaf(a2, cf.z, cf.y * cf.y * a);

        float* st0 = s_stage[w][0];
        float* st1 = s_stage[w][1];
        float* st2 = s_stage[w][2];
        float* st3 = s_stage[w][3];
#pragma unroll
        for (int d = 0; d < 7; d++) {
            float v1 = qd[d] * a;
            float v2 = fmaf(qdd[d], a2, qd[d] * c1v);
            float v3 = fmaf(qddd[d], a3, fmaf(qdd[d], c2v, qd[d] * c3v));
            st0[1 + 7 * lane + d] = q[d];   // conflict-free (gcd(7,32)=1)
            st1[1 + 7 * lane + d] = v1;
            st2[1 + 7 * lane + d] = v2;
            st3[1 + 7 * lane + d] = v3;
            accd[d]   += huber_pos(fmaxf(fabsf(v1) - s_lims[d],      0.0f)) * dt;
            accdd[d]  += huber_pos(fmaxf(fabsf(v2) - s_lims[7 + d],  0.0f)) * dt;
            accddd[d] += huber_pos(fmaxf(fabsf(v3) - s_lims[14 + d], 0.0f)) * dt;
        }
        __syncwarp();

        const size_t chunk = ((size_t)b * NT + t0 + 32 * i) * NDOF; // multiple of 224
        flush_chunk(out + OFF_Q      + chunk, st0, lane);
        flush_chunk(out + OFF_QDOT   + chunk, st1, lane);
        flush_chunk(out + OFF_QDDOT  + chunk, st2, lane);
        flush_chunk(out + OFF_QDDDOT + chunk, st3, lane);
        __syncwarp();
    }

    // warp-reduce the 21 loss accumulators (all lanes same b)
#pragma unroll
    for (int d = 0; d < 7; d++) {
#pragma unroll
        for (int off = 16; off; off >>= 1) {
            accd[d]   += __shfl_xor_sync(0xffffffffu, accd[d],   off);
            accdd[d]  += __shfl_xor_sync(0xffffffffu, accdd[d],  off);
            accddd[d] += __shfl_xor_sync(0xffffffffu, accddd[d], off);
        }
    }
    if (lane == 0) {
#pragma unroll
        for (int d = 0; d < 7; d++) {
            atomicAdd(&out[OFF_QDOT_LOSS   + (size_t)b * NDOF + d], accd[d]);
            atomicAdd(&out[OFF_QDDOT_LOSS  + (size_t)b * NDOF + d], accdd[d]);
            atomicAdd(&out[OFF_QDDDOT_LOSS + (size_t)b * NDOF + d], accddd[d]);
        }
    }
}

// ---------------------------------------------------------------------------
// Kernel D: model_loss = sum of q_dot/q_ddot/q_dddot losses (21504 floats)
// ---------------------------------------------------------------------------
__global__ __launch_bounds__(1024)
void finalize_kernel(float* __restrict__ out)
{
    __shared__ float s[32];
    float v = 0.0f;
    for (int i = threadIdx.x; i < 3 * NB * NDOF; i += 1024)
        v += out[1 + i];
#pragma unroll
    for (int off = 16; off; off >>= 1) v += __shfl_xor_sync(0xffffffffu, v, off);
    if ((threadIdx.x & 31) == 0) s[threadIdx.x >> 5] = v;
    __syncthreads();
    if (threadIdx.x < 32) {
        v = s[threadIdx.x];
#pragma unroll
        for (int off = 16; off; off >>= 1) v += __shfl_xor_sync(0xffffffffu, v, off);
        if (threadIdx.x == 0) out[OFF_MODEL] = v;
    }
}

// ---------------------------------------------------------------------------
extern "C" void kernel_launch(void* const* d_in, const int* in_sizes, int n_in,
                              void* d_out, int out_size)
{
    const float* q_cps  = (const float*)d_in[0];
    const float* t_cps  = (const float*)d_in[1];
    const float* N      = (const float*)d_in[2];
    const float* dN     = (const float*)d_in[3];
    const float* ddN    = (const float*)d_in[4];
    const float* dddN   = (const float*)d_in[5];
    const float* Nt     = (const float*)d_in[6];
    const float* dNt    = (const float*)d_in[7];
    const float* ddNt   = (const float*)d_in[8];
    const float* Ldot   = (const float*)d_in[9];
    const float* Lddot  = (const float*)d_in[10];
    const float* Ldddot = (const float*)d_in[11];
    // d_in[12] = torque_limits (unused: torque == 0 -> torque_loss == 0)

    float* out = (float*)d_out;

    // zero model_loss + all four loss regions, and the torque output (all zeros)
    cudaMemsetAsync(out, 0, (size_t)OFF_Q * sizeof(float), 0);
    cudaMemsetAsync(out + OFF_TORQUE, 0, QTD * sizeof(float), 0);

    dim3 cgrid(NT / 32, NB / 32);                 // (32, 32)
    coeff_kernel<<<cgrid, 1024>>>(t_cps, Nt, dNt, ddNt, out);

    cumsum_kernel<<<NB, 1024>>>(out);

    dim3 grid(NT / T_TILE, NB / B_TILE);          // (16, 128)
    main_kernel<<<grid, THR>>>(q_cps, N, dN, ddN, dddN,
                               Ldot, Lddot, Ldddot, out);

    finalize_kernel<<<1, 1024>>>(out);
}